// round 2
// baseline (speedup 1.0000x reference)
#include <cuda_runtime.h>
#include <cuda_bf16.h>
#include <cstdint>

// Problem dims
#define BB 8
#define SS 2048
#define DIN 1024
#define DOUT 64
#define ROWS_TOTAL (BB * SS)   // 16384

// Scratch for projected q/k/v  (3 x 4 MB device globals; no allocs allowed)
__device__ float g_q[ROWS_TOTAL * DOUT];
__device__ float g_k[ROWS_TOTAL * DOUT];
__device__ float g_v[ROWS_TOTAL * DOUT];

// Mask dtype flag: 0 = uint8/bool, 1 = int32, 2 = float32
__device__ int g_mask_kind;

// ---------------------------------------------------------------------------
// Kernel 0: sniff the mask buffer's element dtype.
// Reads the first 4096 words (16 KB — valid under every candidate dtype,
// since the buffer holds 16384 elements of >= 1 byte).
//   f32 bool: nonzero words are exactly 0x3F800000
//   u8  bool: words pack 4 flags -> some word has a byte set above byte 0
//   i32 bool: every word is 0 or 1
// ---------------------------------------------------------------------------
__global__ void detect_mask_kernel(const unsigned int* __restrict__ m)
{
    __shared__ int sawF, sawHigh;
    if (threadIdx.x == 0) { sawF = 0; sawHigh = 0; }
    __syncthreads();
    for (int i = threadIdx.x; i < 4096; i += 256) {
        unsigned int w = m[i];
        if (w == 0x3F800000u) sawF = 1;
        else if (w & 0xFFFFFF00u) sawHigh = 1;
    }
    __syncthreads();
    if (threadIdx.x == 0)
        g_mask_kind = sawF ? 2 : (sawHigh ? 0 : 1);
}

// ---------------------------------------------------------------------------
// Kernel 1: fused QKV projection.  out[row, n] = seq[row,:] @ W[:,n] + b[n]
// Tile: 64 rows x 64 cols, K-step 16. 256 threads, 4x4 micro-tile per thread.
// ---------------------------------------------------------------------------
__global__ __launch_bounds__(256) void qkv_kernel(
    const float* __restrict__ seq,
    const float* __restrict__ Wq, const float* __restrict__ bq,
    const float* __restrict__ Wk, const float* __restrict__ bk,
    const float* __restrict__ Wv, const float* __restrict__ bv)
{
    __shared__ float As[16][68];   // [kk][m]  (transposed seq tile)
    __shared__ float Bs[16][68];   // [kk][n]

    const float* W;
    const float* bias;
    float* out;
    if (blockIdx.y == 0)      { W = Wq; bias = bq; out = g_q; }
    else if (blockIdx.y == 1) { W = Wk; bias = bk; out = g_k; }
    else                      { W = Wv; bias = bv; out = g_v; }

    const int row0 = blockIdx.x * 64;
    const int tid  = threadIdx.x;
    const int ty   = tid >> 4;      // 0..15
    const int tx   = tid & 15;      // 0..15

    float c[4][4];
#pragma unroll
    for (int i = 0; i < 4; i++)
#pragma unroll
        for (int j = 0; j < 4; j++) c[i][j] = 0.0f;

    for (int k0 = 0; k0 < DIN; k0 += 16) {
#pragma unroll
        for (int i = 0; i < 4; i++) {
            int e    = tid + i * 256;      // e = m*16 + kk
            int mrow = e >> 4;
            int kk   = e & 15;
            As[kk][mrow] = seq[(size_t)(row0 + mrow) * DIN + k0 + kk];
            int kk2 = e >> 6;              // e = kk*64 + n
            int nn  = e & 63;
            Bs[kk2][nn] = W[(size_t)(k0 + kk2) * DOUT + nn];
        }
        __syncthreads();

#pragma unroll
        for (int kk = 0; kk < 16; kk++) {
            float4 a  = *(const float4*)&As[kk][ty * 4];
            float4 bb = *(const float4*)&Bs[kk][tx * 4];
            const float av[4]  = {a.x, a.y, a.z, a.w};
            const float bvv[4] = {bb.x, bb.y, bb.z, bb.w};
#pragma unroll
            for (int i = 0; i < 4; i++)
#pragma unroll
                for (int j = 0; j < 4; j++)
                    c[i][j] = fmaf(av[i], bvv[j], c[i][j]);
        }
        __syncthreads();
    }

    float bj[4];
#pragma unroll
    for (int j = 0; j < 4; j++) bj[j] = bias[tx * 4 + j];

#pragma unroll
    for (int i = 0; i < 4; i++) {
        float4 r;
        r.x = c[i][0] + bj[0];
        r.y = c[i][1] + bj[1];
        r.z = c[i][2] + bj[2];
        r.w = c[i][3] + bj[3];
        *(float4*)&out[(size_t)(row0 + ty * 4 + i) * DOUT + tx * 4] = r;
    }
}

// ---------------------------------------------------------------------------
// Kernel 2: flash-attention, fp32.
// One block = (batch b, 64-query tile). 256 threads (16x16), 4x4 micro-tiles.
// scale = 1/sqrt(S)  (reference scales by sqrt(q.shape[1]) == sqrt(S)).
// ---------------------------------------------------------------------------
__global__ __launch_bounds__(256) void attn_kernel(
    const void* __restrict__ mask_raw,
    float* __restrict__ out)
{
    extern __shared__ float sm[];
    float (*Qs)[68] = (float (*)[68])(sm);                 // [d][q]
    float (*Ks)[68] = (float (*)[68])(sm + 64 * 68);       // [d][k]
    float (*Vs)[68] = (float (*)[68])(sm + 2 * 64 * 68);   // [k][d]
    float (*Ps)[68] = (float (*)[68])(sm + 3 * 64 * 68);   // [k][q]
    float* Mflag    = sm + 4 * 64 * 68;                    // [64]

    const int b   = blockIdx.y;
    const int q0  = blockIdx.x * 64;
    const int tid = threadIdx.x;
    const int ty  = tid >> 4;   // query group
    const int tx  = tid & 15;   // key / dim group

    const float inv_scale = rsqrtf((float)SS);
    const int   mask_kind = g_mask_kind;

    // Load Q tile transposed: Qs[d][q]
    const float* qptr = g_q + (size_t)(b * SS + q0) * DOUT;
#pragma unroll
    for (int i = 0; i < 16; i++) {
        int e   = tid + i * 256;       // e = row*64 + dd
        int row = e >> 6;
        int dd  = e & 63;
        Qs[dd][row] = qptr[e];
    }

    float o[4][4];
    float m[4], l[4];
#pragma unroll
    for (int i = 0; i < 4; i++) {
        m[i] = -1e9f;
        l[i] = 0.0f;
#pragma unroll
        for (int j = 0; j < 4; j++) o[i][j] = 0.0f;
    }

    for (int k0 = 0; k0 < SS; k0 += 64) {
        __syncthreads();   // protect Ks/Vs (and first-iter Qs) from prior readers

        const float* kptr = g_k + (size_t)(b * SS + k0) * DOUT;
        const float* vptr = g_v + (size_t)(b * SS + k0) * DOUT;
#pragma unroll
        for (int i = 0; i < 16; i++) {
            int e   = tid + i * 256;
            int row = e >> 6;
            int dd  = e & 63;
            Ks[dd][row] = kptr[e];     // transposed
            Vs[row][dd] = vptr[e];     // natural
        }
        if (tid < 64) {
            int idx = b * SS + k0 + tid;
            bool mk;
            if (mask_kind == 2)      mk = ((const float*)mask_raw)[idx] != 0.0f;
            else if (mask_kind == 1) mk = ((const int*)mask_raw)[idx] != 0;
            else                     mk = ((const unsigned char*)mask_raw)[idx] != 0;
            Mflag[tid] = mk ? 1.0f : 0.0f;
        }
        __syncthreads();

        // --- scores GEMM: s[q][k] = sum_d Q[q][d] * K[k][d] ---
        float s[4][4];
#pragma unroll
        for (int i = 0; i < 4; i++)
#pragma unroll
            for (int j = 0; j < 4; j++) s[i][j] = 0.0f;

#pragma unroll 8
        for (int dd = 0; dd < 64; dd++) {
            float4 a  = *(const float4*)&Qs[dd][ty * 4];
            float4 bb = *(const float4*)&Ks[dd][tx * 4];
            const float av[4]  = {a.x, a.y, a.z, a.w};
            const float bvv[4] = {bb.x, bb.y, bb.z, bb.w};
#pragma unroll
            for (int i = 0; i < 4; i++)
#pragma unroll
                for (int j = 0; j < 4; j++)
                    s[i][j] = fmaf(av[i], bvv[j], s[i][j]);
        }

        // --- scale + mask ---
        float mf[4];
#pragma unroll
        for (int j = 0; j < 4; j++) mf[j] = Mflag[tx * 4 + j];
#pragma unroll
        for (int i = 0; i < 4; i++)
#pragma unroll
            for (int j = 0; j < 4; j++) {
                float v = s[i][j] * inv_scale;
                s[i][j] = (mf[j] != 0.0f) ? -1e9f : v;
            }

        // --- online softmax per query row (row spread over 16 tx lanes) ---
#pragma unroll
        for (int i = 0; i < 4; i++) {
            float rmax = fmaxf(fmaxf(s[i][0], s[i][1]), fmaxf(s[i][2], s[i][3]));
#pragma unroll
            for (int off = 8; off >= 1; off >>= 1)
                rmax = fmaxf(rmax, __shfl_xor_sync(0xffffffffu, rmax, off, 16));
            float mn    = fmaxf(m[i], rmax);
            float alpha = __expf(m[i] - mn);
            float rs = 0.0f;
#pragma unroll
            for (int j = 0; j < 4; j++) {
                float p = __expf(s[i][j] - mn);
                s[i][j] = p;
                rs += p;
            }
#pragma unroll
            for (int off = 8; off >= 1; off >>= 1)
                rs += __shfl_xor_sync(0xffffffffu, rs, off, 16);
            l[i] = l[i] * alpha + rs;
            m[i] = mn;
#pragma unroll
            for (int j = 0; j < 4; j++) o[i][j] *= alpha;
        }

        // store P transposed: Ps[k][q]
#pragma unroll
        for (int i = 0; i < 4; i++)
#pragma unroll
            for (int j = 0; j < 4; j++)
                Ps[tx * 4 + j][ty * 4 + i] = s[i][j];
        __syncthreads();

        // --- PV GEMM: o[q][d] += sum_k P[q][k] * V[k][d] ---
#pragma unroll 8
        for (int kk = 0; kk < 64; kk++) {
            float4 a  = *(const float4*)&Ps[kk][ty * 4];
            float4 vv = *(const float4*)&Vs[kk][tx * 4];
            const float av[4]  = {a.x, a.y, a.z, a.w};
            const float vvv[4] = {vv.x, vv.y, vv.z, vv.w};
#pragma unroll
            for (int i = 0; i < 4; i++)
#pragma unroll
                for (int j = 0; j < 4; j++)
                    o[i][j] = fmaf(av[i], vvv[j], o[i][j]);
        }
    }

    // epilogue: divide by l, write out
#pragma unroll
    for (int i = 0; i < 4; i++) {
        float invl = 1.0f / l[i];
        float4 r;
        r.x = o[i][0] * invl;
        r.y = o[i][1] * invl;
        r.z = o[i][2] * invl;
        r.w = o[i][3] * invl;
        *(float4*)&out[((size_t)(b * SS) + q0 + ty * 4 + i) * DOUT + tx * 4] = r;
    }
}

// ---------------------------------------------------------------------------
extern "C" void kernel_launch(void* const* d_in, const int* in_sizes, int n_in,
                              void* d_out, int out_size)
{
    const float* seq  = (const float*)d_in[0];
    const void*  mask = d_in[1];
    const float* Wq   = (const float*)d_in[2];
    const float* bq   = (const float*)d_in[3];
    const float* Wk   = (const float*)d_in[4];
    const float* bk   = (const float*)d_in[5];
    const float* Wv   = (const float*)d_in[6];
    const float* bv   = (const float*)d_in[7];
    float* out = (float*)d_out;

    const int attn_smem = (4 * 64 * 68 + 64) * (int)sizeof(float);
    cudaFuncSetAttribute(attn_kernel,
                         cudaFuncAttributeMaxDynamicSharedMemorySize,
                         attn_smem);

    detect_mask_kernel<<<1, 256>>>((const unsigned int*)mask);
    qkv_kernel<<<dim3(ROWS_TOTAL / 64, 3), 256>>>(seq, Wq, bq, Wk, bk, Wv, bv);
    attn_kernel<<<dim3(SS / 64, BB), 256, attn_smem>>>(mask, out);
}